// round 12
// baseline (speedup 1.0000x reference)
#include <cuda_runtime.h>
#include <cuda_fp16.h>
#include <cstdint>

#define NCH 1089
#define NG  76
#define TSTRW 68
#define T_WORDS (256*TSTRW)          // 17408
#define BSTRW 36
#define B_WORDS (128*BSTRW)          // 4608
#define BW  T_WORDS
#define OW  (BW + 2*B_WORDS)         // 26624
#define W2W (OW + 128)               // 26752 : W2 fp32 [128][128]
#define SMEM_WORDS (W2W + 16384)     // 43136
#define SMEM_BYTES (SMEM_WORDS*4)    // 172544

__device__ float g_part[NG * 256 * 128];   // [g][m][n]
__device__ int g_cnt = 0;
__device__ volatile int g_gen = 0;

__device__ __forceinline__ uint32_t smem_u32(const void* p) {
    uint32_t a;
    asm("{ .reg .u64 t; cvta.to.shared.u64 t, %1; cvt.u32.u64 %0, t; }" : "=r"(a) : "l"(p));
    return a;
}
#define CP16(dst, src) asm volatile("cp.async.cg.shared.global [%0], [%1], 16;" :: "r"(dst), "l"(src))
#define CP_COMMIT()    asm volatile("cp.async.commit_group;")

// ---------------------------------------------------------------------------
__global__ void __launch_bounds__(512, 1)
tfn_fused(const float* __restrict__ audio, const float* __restrict__ video,
          const float* __restrict__ text, const float* __restrict__ W1,
          const float* __restrict__ b1, const float* __restrict__ W2,
          const float* __restrict__ b2, const float* __restrict__ W3,
          const float* __restrict__ b3, float* __restrict__ out) {
    extern __shared__ uint32_t sw[];
    const uint32_t sb = smem_u32(sw);
    const int tid = threadIdx.x;
    const int w = tid >> 5, lane = tid & 31;
    const int grp = lane >> 2, tg = lane & 3;
    const int slice = blockIdx.x;            // 0/1 : 64-col N slice
    const int g     = blockIdx.y;            // 0..75 : chunk group

    const int kr = tid >> 4, c4 = tid & 15;
    const uint32_t bh0 = sb + BW * 4;

    // ---- LDG chunk 0 -> regs
    float4 wv[4]; float4 ov = make_float4(0.f, 0.f, 0.f, 0.f);
    {
        const float* Wc = W1 + (size_t)g * 16512 + slice * 64;
        #pragma unroll
        for (int t = 0; t < 4; t++)
            wv[t] = __ldg((const float4*)(Wc + (size_t)(kr + 32 * t + 1) * 128 + c4 * 4));
        if (tid < 16) ov = __ldg((const float4*)(Wc + tid * 4));
    }

    // ---- build T fp16 in smem once
    {
        const float* src = text + (size_t)(tid >> 1) * 128 + (tid & 1) * 64;
        uint32_t dst = sb + (uint32_t)((tid >> 1) * TSTRW + (tid & 1) * 32) * 4;
        #pragma unroll
        for (int j = 0; j < 16; j++) {
            float4 v = __ldg((const float4*)(src + j * 4));
            uint32_t p0, p1;
            asm("cvt.rn.f16x2.f32 %0, %1, %2;" : "=r"(p0) : "f"(v.y), "f"(v.x));
            asm("cvt.rn.f16x2.f32 %0, %1, %2;" : "=r"(p1) : "f"(v.w), "f"(v.z));
            asm volatile("st.shared.v2.b32 [%0], {%1,%2};"
                :: "r"(dst + j * 8), "r"(p0), "r"(p1) : "memory");
        }
    }

    // ---- STS chunk 0 -> buf 0
    {
        #pragma unroll
        for (int t = 0; t < 4; t++) {
            uint32_t p0, p1;
            asm("cvt.rn.f16x2.f32 %0, %1, %2;" : "=r"(p0) : "f"(wv[t].y), "f"(wv[t].x));
            asm("cvt.rn.f16x2.f32 %0, %1, %2;" : "=r"(p1) : "f"(wv[t].w), "f"(wv[t].z));
            asm volatile("st.shared.v2.b32 [%0], {%1,%2};"
                :: "r"(bh0 + (uint32_t)((kr + 32 * t) * BSTRW + 2 * c4) * 4),
                   "r"(p0), "r"(p1) : "memory");
        }
        if (tid < 16)
            asm volatile("st.shared.v4.f32 [%0], {%1,%2,%3,%4};"
                :: "r"(sb + (uint32_t)(OW + tid * 4) * 4),
                   "f"(ov.x), "f"(ov.y), "f"(ov.z), "f"(ov.w) : "memory");
    }
    __syncthreads();

    const int nch = (NCH - g + NG - 1) / NG;   // 14 or 15

    if (nch > 1) {
        const float* Wn = W1 + (size_t)(g + NG) * 16512 + slice * 64;
        #pragma unroll
        for (int t = 0; t < 4; t++)
            wv[t] = __ldg((const float4*)(Wn + (size_t)(kr + 32 * t + 1) * 128 + c4 * 4));
        if (tid < 16) ov = __ldg((const float4*)(Wn + tid * 4));
    }

    const int row0 = (w << 4) + grp;
    const uint32_t aAddr = sb + (uint32_t)((w * 16 + (lane & 15)) * TSTRW) * 4
                         + ((uint32_t)(lane >> 4) << 4);

    float acc[8][4];
    #pragma unroll
    for (int nt = 0; nt < 8; nt++)
        #pragma unroll
        for (int e = 0; e < 4; e++) acc[nt][e] = 0.0f;

    for (int i = 0; i < nch; i++) {
        const int cc = g + i * NG;
        const int buf = i & 1;

        if (i + 1 < nch) {   // STS chunk i+1 -> buf^1 (hidden under MMA(i))
            const uint32_t bn = bh0 + (uint32_t)(buf ^ 1) * (B_WORDS * 4);
            #pragma unroll
            for (int t = 0; t < 4; t++) {
                uint32_t p0, p1;
                asm("cvt.rn.f16x2.f32 %0, %1, %2;" : "=r"(p0) : "f"(wv[t].y), "f"(wv[t].x));
                asm("cvt.rn.f16x2.f32 %0, %1, %2;" : "=r"(p1) : "f"(wv[t].w), "f"(wv[t].z));
                asm volatile("st.shared.v2.b32 [%0], {%1,%2};"
                    :: "r"(bn + (uint32_t)((kr + 32 * t) * BSTRW + 2 * c4) * 4),
                       "r"(p0), "r"(p1) : "memory");
            }
            if (tid < 16)
                asm volatile("st.shared.v4.f32 [%0], {%1,%2,%3,%4};"
                    :: "r"(sb + (uint32_t)(OW + (buf ^ 1) * 64 + tid * 4) * 4),
                       "f"(ov.x), "f"(ov.y), "f"(ov.z), "f"(ov.w) : "memory");
        }
        if (i + 2 < nch) {   // LDG chunk i+2 -> regs
            const float* Wn = W1 + (size_t)(cc + 2 * NG) * 16512 + slice * 64;
            #pragma unroll
            for (int t = 0; t < 4; t++)
                wv[t] = __ldg((const float4*)(Wn + (size_t)(kr + 32 * t + 1) * 128 + c4 * 4));
            if (tid < 16) ov = __ldg((const float4*)(Wn + tid * 4));
        }

        const int ai = cc / 33, vi = cc - ai * 33;
        float s0, s1;
        {
            float av0 = (ai == 0) ? 1.0f : __ldg(&audio[row0 * 32 + ai - 1]);
            float vv0 = (vi == 0) ? 1.0f : __ldg(&video[row0 * 32 + vi - 1]);
            float av1 = (ai == 0) ? 1.0f : __ldg(&audio[(row0 + 8) * 32 + ai - 1]);
            float vv1 = (vi == 0) ? 1.0f : __ldg(&video[(row0 + 8) * 32 + vi - 1]);
            s0 = av0 * vv0; s1 = av1 * vv1;
        }

        float tacc[8][4];
        #pragma unroll
        for (int nt = 0; nt < 8; nt++)
            #pragma unroll
            for (int e = 0; e < 4; e++) tacc[nt][e] = 0.0f;

        const uint32_t bb = bh0 + (uint32_t)buf * (B_WORDS * 4);
        #pragma unroll
        for (int kt = 0; kt < 8; kt++) {
            uint32_t a0, a1, a2, a3;
            asm volatile("ldmatrix.sync.aligned.m8n8.x4.shared.b16 {%0,%1,%2,%3}, [%4];"
                : "=r"(a0), "=r"(a1), "=r"(a2), "=r"(a3)
                : "r"(aAddr + (uint32_t)kt * 32));
            const uint32_t bRow = bb + (uint32_t)((kt * 16 + (lane & 15)) * BSTRW) * 4
                                + ((uint32_t)(lane >> 4) << 4);
            #pragma unroll
            for (int np = 0; np < 4; np++) {
                uint32_t r0, r1, r2, r3;
                asm volatile("ldmatrix.sync.aligned.m8n8.x4.trans.shared.b16 {%0,%1,%2,%3}, [%4];"
                    : "=r"(r0), "=r"(r1), "=r"(r2), "=r"(r3)
                    : "r"(bRow + (uint32_t)np * 32));
                asm volatile(
                    "mma.sync.aligned.m16n8k16.row.col.f32.f16.f16.f32 "
                    "{%0,%1,%2,%3}, {%4,%5,%6,%7}, {%8,%9}, {%0,%1,%2,%3};"
                    : "+f"(tacc[2 * np][0]), "+f"(tacc[2 * np][1]),
                      "+f"(tacc[2 * np][2]), "+f"(tacc[2 * np][3])
                    : "r"(a0), "r"(a1), "r"(a2), "r"(a3), "r"(r0), "r"(r1));
                asm volatile(
                    "mma.sync.aligned.m16n8k16.row.col.f32.f16.f16.f32 "
                    "{%0,%1,%2,%3}, {%4,%5,%6,%7}, {%8,%9}, {%0,%1,%2,%3};"
                    : "+f"(tacc[2 * np + 1][0]), "+f"(tacc[2 * np + 1][1]),
                      "+f"(tacc[2 * np + 1][2]), "+f"(tacc[2 * np + 1][3])
                    : "r"(a0), "r"(a1), "r"(a2), "r"(a3), "r"(r2), "r"(r3));
            }
        }

        const float* on = (const float*)sw + OW + buf * 64;
        #pragma unroll
        for (int nt = 0; nt < 8; nt++) {
            float ox = on[nt * 8 + 2 * tg];
            float oy = on[nt * 8 + 2 * tg + 1];
            acc[nt][0] = fmaf(s0, tacc[nt][0] + ox, acc[nt][0]);
            acc[nt][1] = fmaf(s0, tacc[nt][1] + oy, acc[nt][1]);
            acc[nt][2] = fmaf(s1, tacc[nt][2] + ox, acc[nt][2]);
            acc[nt][3] = fmaf(s1, tacc[nt][3] + oy, acc[nt][3]);
        }
        __syncthreads();
    }

    // ---- store split-K partials
    {
        float* part = g_part + (size_t)g * 32768;
        #pragma unroll
        for (int nt = 0; nt < 8; nt++) {
            int col = slice * 64 + nt * 8 + 2 * tg;
            *(float2*)&part[row0 * 128 + col]       = make_float2(acc[nt][0], acc[nt][1]);
            *(float2*)&part[(row0 + 8) * 128 + col] = make_float2(acc[nt][2], acc[nt][3]);
        }
    }

    // ---- stage W2 -> smem (overlaps barrier wait)
    {
        const char* src = (const char*)W2;
        const uint32_t dW = sb + (uint32_t)W2W * 4;
        #pragma unroll
        for (int i2 = 0; i2 < 8; i2++) {
            int task = tid + (i2 << 9);
            CP16(dW + (uint32_t)task * 16, src + (size_t)task * 16);
        }
        CP_COMMIT();
    }

    // ---- grid barrier (152 CTAs, all resident: 1 CTA/SM by smem)
    __threadfence();
    __syncthreads();
    if (tid == 0) {
        int gen0 = g_gen;
        int old = atomicAdd(&g_cnt, 1);
        if (old == 151) {
            g_cnt = 0;
            __threadfence();
            g_gen = gen0 + 1;
        } else {
            while (g_gen == gen0) __nanosleep(64);
        }
        __threadfence();
    }
    __syncthreads();

    // ---- epilogue phase: rows r = bid, bid+152
    asm volatile("cp.async.wait_group 0;");
    __syncthreads();

    float* smf  = (float*)sw;        // reuse T region
    float* ps   = smf;               // [16][128]
    float* h1s  = smf + 2048;        // [128]
    float* psum = smf + 2176;        // [4][128]
    float* red  = smf + 2688;        // [4]
    const float* W2s = (const float*)sw + W2W;
    const int bid = blockIdx.x + blockIdx.y * 2;

    for (int r = bid; r < 256; r += 152) {
        {   // 16-bucket float4 split-K reduce
            const int q = tid & 31, s = tid >> 5;
            float4 sum = make_float4(0.f, 0.f, 0.f, 0.f);
            const float* base = g_part + (size_t)r * 128 + q * 4;
            #pragma unroll 5
            for (int gg = s; gg < NG; gg += 16) {
                float4 v = __ldg((const float4*)(base + (size_t)gg * 32768));
                sum.x += v.x; sum.y += v.y; sum.z += v.z; sum.w += v.w;
            }
            *(float4*)&ps[s * 128 + q * 4] = sum;
        }
        __syncthreads();

        if (tid < 128) {
            float sum = __ldg(&b1[tid]);
            #pragma unroll
            for (int s = 0; s < 16; s++) sum += ps[s * 128 + tid];
            h1s[tid] = fmaxf(sum, 0.0f);
        }
        __syncthreads();

        {   // L2: quarter-k split
            const int p = tid & 127, kq = tid >> 7, k0 = kq << 5;
            float a = 0.0f;
            #pragma unroll 8
            for (int k = 0; k < 32; k++)
                a = fmaf(h1s[k0 + k], W2s[(k0 + k) * 128 + p], a);
            psum[kq * 128 + p] = a;
        }
        __syncthreads();

        if (tid < 128) {
            float h2 = fmaxf(psum[tid] + psum[128 + tid] + psum[256 + tid]
                             + psum[384 + tid] + __ldg(&b2[tid]), 0.0f) * __ldg(&W3[tid]);
            #pragma unroll
            for (int o = 16; o > 0; o >>= 1) h2 += __shfl_down_sync(0xffffffff, h2, o);
            if ((tid & 31) == 0) red[tid >> 5] = h2;
        }
        __syncthreads();
        if (tid == 0) out[r] = red[0] + red[1] + red[2] + red[3] + __ldg(&b3[0]);
        __syncthreads();
    }
}

// ---------------------------------------------------------------------------
extern "C" void kernel_launch(void* const* d_in, const int* in_sizes, int n_in,
                              void* d_out, int out_size) {
    (void)in_sizes; (void)n_in; (void)out_size;
    const float* audio = (const float*)d_in[0];
    const float* video = (const float*)d_in[1];
    const float* text  = (const float*)d_in[2];
    const float* W1    = (const float*)d_in[3];
    const float* b1    = (const float*)d_in[4];
    const float* W2    = (const float*)d_in[5];
    const float* b2    = (const float*)d_in[6];
    const float* W3    = (const float*)d_in[7];
    const float* b3    = (const float*)d_in[8];
    float* out = (float*)d_out;

    cudaFuncSetAttribute(tfn_fused, cudaFuncAttributeMaxDynamicSharedMemorySize,
                         SMEM_BYTES);

    dim3 grid(2, NG);   // 152 CTAs = one wave, all co-resident
    tfn_fused<<<grid, 512, SMEM_BYTES>>>(audio, video, text, W1, b1, W2, b2,
                                         W3, b3, out);
}

// round 13
// speedup vs baseline: 1.0412x; 1.0412x over previous
#include <cuda_runtime.h>
#include <cuda_fp16.h>
#include <cstdint>

#define NCH 1089
#define NG  76
#define TSTRW 68
#define T_WORDS (256*TSTRW)
#define BSTRW 36
#define B_WORDS (128*BSTRW)
#define BW  T_WORDS
#define OW  (BW + 2*B_WORDS)
#define SMEM_WORDS (OW + 128)
#define SMEM_BYTES (SMEM_WORDS*4)

__device__ float g_part[NG * 256 * 128];   // [g][m][n]

__device__ __forceinline__ uint32_t smem_u32(const void* p) {
    uint32_t a;
    asm("{ .reg .u64 t; cvta.to.shared.u64 t, %1; cvt.u32.u64 %0, t; }" : "=r"(a) : "l"(p));
    return a;
}
#define CP16(dst, src) asm volatile("cp.async.cg.shared.global [%0], [%1], 16;" :: "r"(dst), "l"(src))
#define CP_COMMIT()    asm volatile("cp.async.commit_group;")

// ---------------------------------------------------------------------------
__global__ void __launch_bounds__(512, 1)
tfn_gemm(const float* __restrict__ audio, const float* __restrict__ video,
         const float* __restrict__ text, const float* __restrict__ W1) {
    extern __shared__ uint32_t sw[];
    const uint32_t sb = smem_u32(sw);
    const int tid = threadIdx.x;
    const int w = tid >> 5, lane = tid & 31;
    const int grp = lane >> 2, tg = lane & 3;
    const int slice = blockIdx.x;            // 0/1 : 64-col N slice
    const int g     = blockIdx.y;            // 0..75 : chunk group

    const int kr = tid >> 4, c4 = tid & 15;
    const uint32_t bh0 = sb + BW * 4;

    // LDG chunk 0 -> regs
    float4 wv[4]; float4 ov = make_float4(0.f, 0.f, 0.f, 0.f);
    {
        const float* Wc = W1 + (size_t)g * 16512 + slice * 64;
        #pragma unroll
        for (int t = 0; t < 4; t++)
            wv[t] = __ldg((const float4*)(Wc + (size_t)(kr + 32 * t + 1) * 128 + c4 * 4));
        if (tid < 16) ov = __ldg((const float4*)(Wc + tid * 4));
    }

    // build T fp16 in smem once
    {
        const float* src = text + (size_t)(tid >> 1) * 128 + (tid & 1) * 64;
        uint32_t dst = sb + (uint32_t)((tid >> 1) * TSTRW + (tid & 1) * 32) * 4;
        #pragma unroll
        for (int j = 0; j < 16; j++) {
            float4 v = __ldg((const float4*)(src + j * 4));
            uint32_t p0, p1;
            asm("cvt.rn.f16x2.f32 %0, %1, %2;" : "=r"(p0) : "f"(v.y), "f"(v.x));
            asm("cvt.rn.f16x2.f32 %0, %1, %2;" : "=r"(p1) : "f"(v.w), "f"(v.z));
            asm volatile("st.shared.v2.b32 [%0], {%1,%2};"
                :: "r"(dst + j * 8), "r"(p0), "r"(p1) : "memory");
        }
    }

    // STS chunk 0 -> buf 0
    {
        #pragma unroll
        for (int t = 0; t < 4; t++) {
            uint32_t p0, p1;
            asm("cvt.rn.f16x2.f32 %0, %1, %2;" : "=r"(p0) : "f"(wv[t].y), "f"(wv[t].x));
            asm("cvt.rn.f16x2.f32 %0, %1, %2;" : "=r"(p1) : "f"(wv[t].w), "f"(wv[t].z));
            asm volatile("st.shared.v2.b32 [%0], {%1,%2};"
                :: "r"(bh0 + (uint32_t)((kr + 32 * t) * BSTRW + 2 * c4) * 4),
                   "r"(p0), "r"(p1) : "memory");
        }
        if (tid < 16)
            asm volatile("st.shared.v4.f32 [%0], {%1,%2,%3,%4};"
                :: "r"(sb + (uint32_t)(OW + tid * 4) * 4),
                   "f"(ov.x), "f"(ov.y), "f"(ov.z), "f"(ov.w) : "memory");
    }
    __syncthreads();

    const int nch = (NCH - g + NG - 1) / NG;   // 14 or 15

    if (nch > 1) {
        const float* Wn = W1 + (size_t)(g + NG) * 16512 + slice * 64;
        #pragma unroll
        for (int t = 0; t < 4; t++)
            wv[t] = __ldg((const float4*)(Wn + (size_t)(kr + 32 * t + 1) * 128 + c4 * 4));
        if (tid < 16) ov = __ldg((const float4*)(Wn + tid * 4));
    }

    const int row0 = (w << 4) + grp;
    const uint32_t aAddr = sb + (uint32_t)((w * 16 + (lane & 15)) * TSTRW) * 4
                         + ((uint32_t)(lane >> 4) << 4);

    float acc[8][4];
    #pragma unroll
    for (int nt = 0; nt < 8; nt++)
        #pragma unroll
        for (int e = 0; e < 4; e++) acc[nt][e] = 0.0f;

    for (int i = 0; i < nch; i++) {
        const int cc = g + i * NG;
        const int buf = i & 1;

        if (i + 1 < nch) {   // STS chunk i+1 -> buf^1 (hidden under MMA(i))
            const uint32_t bn = bh0 + (uint32_t)(buf ^ 1) * (B_WORDS * 4);
            #pragma unroll
            for (int t = 0; t < 4; t++) {
                uint32_t p0, p1;
                asm("cvt.rn.f16x2.f32 %0, %1, %2;" : "=r"(p0) : "f"(wv[t].y), "f"(wv[t].x));
                asm("cvt.rn.f16x2.f32 %0, %1, %2;" : "=r"(p1) : "f"(wv[t].w), "f"(wv[t].z));
                asm volatile("st.shared.v2.b32 [%0], {%1,%2};"
                    :: "r"(bn + (uint32_t)((kr + 32 * t) * BSTRW + 2 * c4) * 4),
                       "r"(p0), "r"(p1) : "memory");
            }
            if (tid < 16)
                asm volatile("st.shared.v4.f32 [%0], {%1,%2,%3,%4};"
                    :: "r"(sb + (uint32_t)(OW + (buf ^ 1) * 64 + tid * 4) * 4),
                       "f"(ov.x), "f"(ov.y), "f"(ov.z), "f"(ov.w) : "memory");
        }
        if (i + 2 < nch) {   // LDG chunk i+2 -> regs
            const float* Wn = W1 + (size_t)(cc + 2 * NG) * 16512 + slice * 64;
            #pragma unroll
            for (int t = 0; t < 4; t++)
                wv[t] = __ldg((const float4*)(Wn + (size_t)(kr + 32 * t + 1) * 128 + c4 * 4));
            if (tid < 16) ov = __ldg((const float4*)(Wn + tid * 4));
        }

        const int ai = cc / 33, vi = cc - ai * 33;
        float s0, s1;
        {
            float av0 = (ai == 0) ? 1.0f : __ldg(&audio[row0 * 32 + ai - 1]);
            float vv0 = (vi == 0) ? 1.0f : __ldg(&video[row0 * 32 + vi - 1]);
            float av1 = (ai == 0) ? 1.0f : __ldg(&audio[(row0 + 8) * 32 + ai - 1]);
            float vv1 = (vi == 0) ? 1.0f : __ldg(&video[(row0 + 8) * 32 + vi - 1]);
            s0 = av0 * vv0; s1 = av1 * vv1;
        }

        float tacc[8][4];
        #pragma unroll
        for (int nt = 0; nt < 8; nt++)
            #pragma unroll
            for (int e = 0; e < 4; e++) tacc[nt][e] = 0.0f;

        const uint32_t bb = bh0 + (uint32_t)buf * (B_WORDS * 4);
        #pragma unroll
        for (int kt = 0; kt < 8; kt++) {
            uint32_t a0, a1, a2, a3;
            asm volatile("ldmatrix.sync.aligned.m8n8.x4.shared.b16 {%0,%1,%2,%3}, [%4];"
                : "=r"(a0), "=r"(a1), "=r"(a2), "=r"(a3)
                : "r"(aAddr + (uint32_t)kt * 32));
            const uint32_t bRow = bb + (uint32_t)((kt * 16 + (lane & 15)) * BSTRW) * 4
                                + ((uint32_t)(lane >> 4) << 4);
            #pragma unroll
            for (int np = 0; np < 4; np++) {
                uint32_t r0, r1, r2, r3;
                asm volatile("ldmatrix.sync.aligned.m8n8.x4.trans.shared.b16 {%0,%1,%2,%3}, [%4];"
                    : "=r"(r0), "=r"(r1), "=r"(r2), "=r"(r3)
                    : "r"(bRow + (uint32_t)np * 32));
                asm volatile(
                    "mma.sync.aligned.m16n8k16.row.col.f32.f16.f16.f32 "
                    "{%0,%1,%2,%3}, {%4,%5,%6,%7}, {%8,%9}, {%0,%1,%2,%3};"
                    : "+f"(tacc[2 * np][0]), "+f"(tacc[2 * np][1]),
                      "+f"(tacc[2 * np][2]), "+f"(tacc[2 * np][3])
                    : "r"(a0), "r"(a1), "r"(a2), "r"(a3), "r"(r0), "r"(r1));
                asm volatile(
                    "mma.sync.aligned.m16n8k16.row.col.f32.f16.f16.f32 "
                    "{%0,%1,%2,%3}, {%4,%5,%6,%7}, {%8,%9}, {%0,%1,%2,%3};"
                    : "+f"(tacc[2 * np + 1][0]), "+f"(tacc[2 * np + 1][1]),
                      "+f"(tacc[2 * np + 1][2]), "+f"(tacc[2 * np + 1][3])
                    : "r"(a0), "r"(a1), "r"(a2), "r"(a3), "r"(r2), "r"(r3));
            }
        }

        const float* on = (const float*)sw + OW + buf * 64;
        #pragma unroll
        for (int nt = 0; nt < 8; nt++) {
            float ox = on[nt * 8 + 2 * tg];
            float oy = on[nt * 8 + 2 * tg + 1];
            acc[nt][0] = fmaf(s0, tacc[nt][0] + ox, acc[nt][0]);
            acc[nt][1] = fmaf(s0, tacc[nt][1] + oy, acc[nt][1]);
            acc[nt][2] = fmaf(s1, tacc[nt][2] + ox, acc[nt][2]);
            acc[nt][3] = fmaf(s1, tacc[nt][3] + oy, acc[nt][3]);
        }
        __syncthreads();
    }

    float* part = g_part + (size_t)g * 32768;
    #pragma unroll
    for (int nt = 0; nt < 8; nt++) {
        int col = slice * 64 + nt * 8 + 2 * tg;
        *(float2*)&part[row0 * 128 + col]       = make_float2(acc[nt][0], acc[nt][1]);
        *(float2*)&part[(row0 + 8) * 128 + col] = make_float2(acc[nt][2], acc[nt][3]);
    }
}

// ---------------------------------------------------------------------------
// epi v4: 64 CTAs x 512 threads, 4 rows/CTA. W2 staged once per CTA.
#define EPI_FLOATS (16384 + 2048 + 512 + 16)
#define EPI_BYTES  (EPI_FLOATS * 4)
__global__ void __launch_bounds__(512)
epi(const float* __restrict__ b1, const float* __restrict__ W2,
    const float* __restrict__ b2, const float* __restrict__ W3,
    const float* __restrict__ b3, float* __restrict__ out) {
    extern __shared__ float smf[];
    float* W2s = smf;            // 16384
    float* ps  = smf + 16384;    // [4 rows][4 buckets][128]
    float* h1s = ps + 2048;      // [4][128]
    float* red = h1s + 512;      // [16]
    const int t = threadIdx.x;
    const int r0 = blockIdx.x * 4;

    {   // stage W2 (overlaps reduce)
        const char* src = (const char*)W2;
        const uint32_t dW = smem_u32(W2s);
        #pragma unroll
        for (int i = 0; i < 8; i++) {
            int task = t + (i << 9);
            CP16(dW + (uint32_t)task * 16, src + (size_t)task * 16);
        }
        CP_COMMIT();
    }

    const int row = t >> 7;          // 0..3
    const int p   = t & 127;

    {   // split-K reduce: bucket s (0..3) sums groups {s, s+4, ...} (19 each)
        const int s = (t >> 5) & 3, q = t & 31;
        float4 sum = make_float4(0.f, 0.f, 0.f, 0.f);
        const float* base = g_part + (size_t)(r0 + row) * 128 + q * 4;
        #pragma unroll
        for (int gg = s; gg < NG; gg += 4) {
            float4 v = __ldg((const float4*)(base + (size_t)gg * 32768));
            sum.x += v.x; sum.y += v.y; sum.z += v.z; sum.w += v.w;
        }
        *(float4*)&ps[(row * 4 + s) * 128 + q * 4] = sum;
    }
    asm volatile("cp.async.wait_group 0;");
    __syncthreads();

    // L1 bias + relu
    {
        float sum = __ldg(&b1[p]);
        #pragma unroll
        for (int s = 0; s < 4; s++) sum += ps[(row * 4 + s) * 128 + p];
        h1s[row * 128 + p] = fmaxf(sum, 0.0f);
    }
    __syncthreads();

    // L2: one output per thread, split accumulators for ILP
    float a0 = 0.0f, a1 = 0.0f;
    {
        const float* hr = h1s + row * 128;
        #pragma unroll 16
        for (int k = 0; k < 128; k += 2) {
            a0 = fmaf(hr[k],     W2s[k * 128 + p],       a0);
            a1 = fmaf(hr[k + 1], W2s[(k + 1) * 128 + p], a1);
        }
    }

    // L3: relu(h2)*W3, warp shuffle reduce, 4 warps per row
    {
        float h2 = fmaxf(a0 + a1 + __ldg(&b2[p]), 0.0f) * __ldg(&W3[p]);
        #pragma unroll
        for (int o = 16; o > 0; o >>= 1) h2 += __shfl_down_sync(0xffffffff, h2, o);
        if ((t & 31) == 0) red[t >> 5] = h2;
    }
    __syncthreads();
    if (t < 4)
        out[r0 + t] = red[t * 4] + red[t * 4 + 1] + red[t * 4 + 2] + red[t * 4 + 3]
                    + __ldg(&b3[0]);
}

// ---------------------------------------------------------------------------
extern "C" void kernel_launch(void* const* d_in, const int* in_sizes, int n_in,
                              void* d_out, int out_size) {
    (void)in_sizes; (void)n_in; (void)out_size;
    const float* audio = (const float*)d_in[0];
    const float* video = (const float*)d_in[1];
    const float* text  = (const float*)d_in[2];
    const float* W1    = (const float*)d_in[3];
    const float* b1    = (const float*)d_in[4];
    const float* W2    = (const float*)d_in[5];
    const float* b2    = (const float*)d_in[6];
    const float* W3    = (const float*)d_in[7];
    const float* b3    = (const float*)d_in[8];
    float* out = (float*)d_out;

    cudaFuncSetAttribute(tfn_gemm, cudaFuncAttributeMaxDynamicSharedMemorySize,
                         SMEM_BYTES);
    cudaFuncSetAttribute(epi, cudaFuncAttributeMaxDynamicSharedMemorySize,
                         EPI_BYTES);

    dim3 grid(2, NG);   // 152 CTAs = one wave
    tfn_gemm<<<grid, 512, SMEM_BYTES>>>(audio, video, text, W1);
    epi<<<64, 512, EPI_BYTES>>>(b1, W2, b2, W3, b3, out);
}

// round 14
// speedup vs baseline: 1.0868x; 1.0437x over previous
#include <cuda_runtime.h>
#include <cuda_fp16.h>
#include <cstdint>

#define NCH 1089
#define NG  76
#define TSTRW 68
#define T_WORDS (256*TSTRW)
#define BSTRW 36
#define B_WORDS (128*BSTRW)
#define BW  T_WORDS
#define OW  (BW + 2*B_WORDS)
#define SMEM_WORDS (OW + 128)
#define SMEM_BYTES (SMEM_WORDS*4)

__device__ float g_part[NG * 256 * 128];   // [g][m][n]

__device__ __forceinline__ uint32_t smem_u32(const void* p) {
    uint32_t a;
    asm("{ .reg .u64 t; cvta.to.shared.u64 t, %1; cvt.u32.u64 %0, t; }" : "=r"(a) : "l"(p));
    return a;
}
#define CP16(dst, src) asm volatile("cp.async.cg.shared.global [%0], [%1], 16;" :: "r"(dst), "l"(src))
#define CP_COMMIT()    asm volatile("cp.async.commit_group;")

// ---------------------------------------------------------------------------
__global__ void __launch_bounds__(512, 1)
tfn_gemm(const float* __restrict__ audio, const float* __restrict__ video,
         const float* __restrict__ text, const float* __restrict__ W1) {
    extern __shared__ uint32_t sw[];
    const uint32_t sb = smem_u32(sw);
    const int tid = threadIdx.x;
    const int w = tid >> 5, lane = tid & 31;
    const int grp = lane >> 2, tg = lane & 3;
    const int slice = blockIdx.x;            // 0/1 : 64-col N slice
    const int g     = blockIdx.y;            // 0..75 : chunk group

    const int kr = tid >> 4, c4 = tid & 15;
    const uint32_t bh0 = sb + BW * 4;

    // LDG chunk 0 -> regs
    float4 wv[4]; float4 ov = make_float4(0.f, 0.f, 0.f, 0.f);
    {
        const float* Wc = W1 + (size_t)g * 16512 + slice * 64;
        #pragma unroll
        for (int t = 0; t < 4; t++)
            wv[t] = __ldg((const float4*)(Wc + (size_t)(kr + 32 * t + 1) * 128 + c4 * 4));
        if (tid < 16) ov = __ldg((const float4*)(Wc + tid * 4));
    }

    // build T fp16 in smem once
    {
        const float* src = text + (size_t)(tid >> 1) * 128 + (tid & 1) * 64;
        uint32_t dst = sb + (uint32_t)((tid >> 1) * TSTRW + (tid & 1) * 32) * 4;
        #pragma unroll
        for (int j = 0; j < 16; j++) {
            float4 v = __ldg((const float4*)(src + j * 4));
            uint32_t p0, p1;
            asm("cvt.rn.f16x2.f32 %0, %1, %2;" : "=r"(p0) : "f"(v.y), "f"(v.x));
            asm("cvt.rn.f16x2.f32 %0, %1, %2;" : "=r"(p1) : "f"(v.w), "f"(v.z));
            asm volatile("st.shared.v2.b32 [%0], {%1,%2};"
                :: "r"(dst + j * 8), "r"(p0), "r"(p1) : "memory");
        }
    }

    // STS chunk 0 -> buf 0
    {
        #pragma unroll
        for (int t = 0; t < 4; t++) {
            uint32_t p0, p1;
            asm("cvt.rn.f16x2.f32 %0, %1, %2;" : "=r"(p0) : "f"(wv[t].y), "f"(wv[t].x));
            asm("cvt.rn.f16x2.f32 %0, %1, %2;" : "=r"(p1) : "f"(wv[t].w), "f"(wv[t].z));
            asm volatile("st.shared.v2.b32 [%0], {%1,%2};"
                :: "r"(bh0 + (uint32_t)((kr + 32 * t) * BSTRW + 2 * c4) * 4),
                   "r"(p0), "r"(p1) : "memory");
        }
        if (tid < 16)
            asm volatile("st.shared.v4.f32 [%0], {%1,%2,%3,%4};"
                :: "r"(sb + (uint32_t)(OW + tid * 4) * 4),
                   "f"(ov.x), "f"(ov.y), "f"(ov.z), "f"(ov.w) : "memory");
    }
    __syncthreads();

    const int nch = (NCH - g + NG - 1) / NG;   // 14 or 15

    if (nch > 1) {
        const float* Wn = W1 + (size_t)(g + NG) * 16512 + slice * 64;
        #pragma unroll
        for (int t = 0; t < 4; t++)
            wv[t] = __ldg((const float4*)(Wn + (size_t)(kr + 32 * t + 1) * 128 + c4 * 4));
        if (tid < 16) ov = __ldg((const float4*)(Wn + tid * 4));
    }

    const int row0 = (w << 4) + grp;
    const uint32_t aAddr = sb + (uint32_t)((w * 16 + (lane & 15)) * TSTRW) * 4
                         + ((uint32_t)(lane >> 4) << 4);

    float acc[8][4];
    #pragma unroll
    for (int nt = 0; nt < 8; nt++)
        #pragma unroll
        for (int e = 0; e < 4; e++) acc[nt][e] = 0.0f;

    for (int i = 0; i < nch; i++) {
        const int cc = g + i * NG;
        const int buf = i & 1;

        if (i + 1 < nch) {   // STS chunk i+1 -> buf^1 (hidden under MMA(i))
            const uint32_t bn = bh0 + (uint32_t)(buf ^ 1) * (B_WORDS * 4);
            #pragma unroll
            for (int t = 0; t < 4; t++) {
                uint32_t p0, p1;
                asm("cvt.rn.f16x2.f32 %0, %1, %2;" : "=r"(p0) : "f"(wv[t].y), "f"(wv[t].x));
                asm("cvt.rn.f16x2.f32 %0, %1, %2;" : "=r"(p1) : "f"(wv[t].w), "f"(wv[t].z));
                asm volatile("st.shared.v2.b32 [%0], {%1,%2};"
                    :: "r"(bn + (uint32_t)((kr + 32 * t) * BSTRW + 2 * c4) * 4),
                       "r"(p0), "r"(p1) : "memory");
            }
            if (tid < 16)
                asm volatile("st.shared.v4.f32 [%0], {%1,%2,%3,%4};"
                    :: "r"(sb + (uint32_t)(OW + (buf ^ 1) * 64 + tid * 4) * 4),
                       "f"(ov.x), "f"(ov.y), "f"(ov.z), "f"(ov.w) : "memory");
        }
        if (i + 2 < nch) {   // LDG chunk i+2 -> regs
            const float* Wn = W1 + (size_t)(cc + 2 * NG) * 16512 + slice * 64;
            #pragma unroll
            for (int t = 0; t < 4; t++)
                wv[t] = __ldg((const float4*)(Wn + (size_t)(kr + 32 * t + 1) * 128 + c4 * 4));
            if (tid < 16) ov = __ldg((const float4*)(Wn + tid * 4));
        }

        const int ai = cc / 33, vi = cc - ai * 33;
        float s0, s1;
        {
            float av0 = (ai == 0) ? 1.0f : __ldg(&audio[row0 * 32 + ai - 1]);
            float vv0 = (vi == 0) ? 1.0f : __ldg(&video[row0 * 32 + vi - 1]);
            float av1 = (ai == 0) ? 1.0f : __ldg(&audio[(row0 + 8) * 32 + ai - 1]);
            float vv1 = (vi == 0) ? 1.0f : __ldg(&video[(row0 + 8) * 32 + vi - 1]);
            s0 = av0 * vv0; s1 = av1 * vv1;
        }

        float tacc[8][4];
        #pragma unroll
        for (int nt = 0; nt < 8; nt++)
            #pragma unroll
            for (int e = 0; e < 4; e++) tacc[nt][e] = 0.0f;

        const uint32_t bb = bh0 + (uint32_t)buf * (B_WORDS * 4);
        #pragma unroll
        for (int kt = 0; kt < 8; kt++) {
            uint32_t a0, a1, a2, a3;
            asm volatile("ldmatrix.sync.aligned.m8n8.x4.shared.b16 {%0,%1,%2,%3}, [%4];"
                : "=r"(a0), "=r"(a1), "=r"(a2), "=r"(a3)
                : "r"(aAddr + (uint32_t)kt * 32));
            const uint32_t bRow = bb + (uint32_t)((kt * 16 + (lane & 15)) * BSTRW) * 4
                                + ((uint32_t)(lane >> 4) << 4);
            #pragma unroll
            for (int np = 0; np < 4; np++) {
                uint32_t r0, r1, r2, r3;
                asm volatile("ldmatrix.sync.aligned.m8n8.x4.trans.shared.b16 {%0,%1,%2,%3}, [%4];"
                    : "=r"(r0), "=r"(r1), "=r"(r2), "=r"(r3)
                    : "r"(bRow + (uint32_t)np * 32));
                asm volatile(
                    "mma.sync.aligned.m16n8k16.row.col.f32.f16.f16.f32 "
                    "{%0,%1,%2,%3}, {%4,%5,%6,%7}, {%8,%9}, {%0,%1,%2,%3};"
                    : "+f"(tacc[2 * np][0]), "+f"(tacc[2 * np][1]),
                      "+f"(tacc[2 * np][2]), "+f"(tacc[2 * np][3])
                    : "r"(a0), "r"(a1), "r"(a2), "r"(a3), "r"(r0), "r"(r1));
                asm volatile(
                    "mma.sync.aligned.m16n8k16.row.col.f32.f16.f16.f32 "
                    "{%0,%1,%2,%3}, {%4,%5,%6,%7}, {%8,%9}, {%0,%1,%2,%3};"
                    : "+f"(tacc[2 * np + 1][0]), "+f"(tacc[2 * np + 1][1]),
                      "+f"(tacc[2 * np + 1][2]), "+f"(tacc[2 * np + 1][3])
                    : "r"(a0), "r"(a1), "r"(a2), "r"(a3), "r"(r2), "r"(r3));
            }
        }

        const float* on = (const float*)sw + OW + buf * 64;
        #pragma unroll
        for (int nt = 0; nt < 8; nt++) {
            float ox = on[nt * 8 + 2 * tg];
            float oy = on[nt * 8 + 2 * tg + 1];
            acc[nt][0] = fmaf(s0, tacc[nt][0] + ox, acc[nt][0]);
            acc[nt][1] = fmaf(s0, tacc[nt][1] + oy, acc[nt][1]);
            acc[nt][2] = fmaf(s1, tacc[nt][2] + ox, acc[nt][2]);
            acc[nt][3] = fmaf(s1, tacc[nt][3] + oy, acc[nt][3]);
        }
        __syncthreads();
    }

    float* part = g_part + (size_t)g * 32768;
    #pragma unroll
    for (int nt = 0; nt < 8; nt++) {
        int col = slice * 64 + nt * 8 + 2 * tg;
        *(float2*)&part[row0 * 128 + col]       = make_float2(acc[nt][0], acc[nt][1]);
        *(float2*)&part[(row0 + 8) * 128 + col] = make_float2(acc[nt][2], acc[nt][3]);
    }
}

// ---------------------------------------------------------------------------
// epi v5: exactly one wave (152 CTAs x 512). CTA b -> rows b and b+152.
// Both rows reduced concurrently (thread split), paired-stream loads (MLP 2).
#define EPI_FLOATS (16384 + 2048 + 256 + 512 + 16)
#define EPI_BYTES  (EPI_FLOATS * 4)
__global__ void __launch_bounds__(512)
epi(const float* __restrict__ b1, const float* __restrict__ W2,
    const float* __restrict__ b2, const float* __restrict__ W3,
    const float* __restrict__ b3, float* __restrict__ out) {
    extern __shared__ float smf[];
    float* W2s  = smf;            // 16384
    float* ps   = smf + 16384;    // [2 rows][8 buckets][128]
    float* h1s  = ps + 2048;      // [2][128]
    float* psum = h1s + 256;      // [2 rows][2 kh][128]
    float* red  = psum + 512;     // [8]
    const int t = threadIdx.x;
    const int r0 = blockIdx.x;                 // always valid
    const int r1 = blockIdx.x + 152;           // valid iff < 256
    const bool has2 = (r1 < 256);

    {   // stage W2 (overlaps reduce)
        const char* src = (const char*)W2;
        const uint32_t dW = smem_u32(W2s);
        #pragma unroll
        for (int i = 0; i < 8; i++) {
            int task = t + (i << 9);
            CP16(dW + (uint32_t)task * 16, src + (size_t)task * 16);
        }
        CP_COMMIT();
    }

    {   // reduce: rs = row-select, s = bucket (pairs s and s+8), q = col quad
        const int q = t & 31, s = (t >> 5) & 7, rs = t >> 8;
        const int r = rs ? (has2 ? r1 : r0) : r0;   // duplicate r0 if no r1 (ignored)
        float4 sA = make_float4(0.f, 0.f, 0.f, 0.f);
        float4 sB = make_float4(0.f, 0.f, 0.f, 0.f);
        const float* base = g_part + (size_t)r * 128 + q * 4;
        #pragma unroll
        for (int gg = s; gg < NG; gg += 16) {
            float4 vA = __ldg((const float4*)(base + (size_t)gg * 32768));
            if (gg + 8 < NG) {
                float4 vB = __ldg((const float4*)(base + (size_t)(gg + 8) * 32768));
                sB.x += vB.x; sB.y += vB.y; sB.z += vB.z; sB.w += vB.w;
            }
            sA.x += vA.x; sA.y += vA.y; sA.z += vA.z; sA.w += vA.w;
        }
        sA.x += sB.x; sA.y += sB.y; sA.z += sB.z; sA.w += sB.w;
        *(float4*)&ps[(rs * 8 + s) * 128 + q * 4] = sA;
    }
    asm volatile("cp.async.wait_group 0;");
    __syncthreads();

    // L1 bias + relu (256 threads: 2 rows x 128 cols)
    if (t < 256) {
        const int row = t >> 7, p = t & 127;
        float sum = __ldg(&b1[p]);
        #pragma unroll
        for (int s = 0; s < 8; s++) sum += ps[(row * 8 + s) * 128 + p];
        h1s[row * 128 + p] = fmaxf(sum, 0.0f);
    }
    __syncthreads();

    // L2: all 512 threads: row = t>>8, k-half = (t>>7)&1, p = t&127
    {
        const int row = t >> 8, kh = (t >> 7) & 1, p = t & 127, k0 = kh << 6;
        const float* hr = h1s + row * 128;
        float a0 = 0.0f, a1 = 0.0f;
        #pragma unroll 16
        for (int k = 0; k < 64; k += 2) {
            a0 = fmaf(hr[k0 + k],     W2s[(k0 + k) * 128 + p],     a0);
            a1 = fmaf(hr[k0 + k + 1], W2s[(k0 + k + 1) * 128 + p], a1);
        }
        psum[(row * 2 + kh) * 128 + p] = a0 + a1;
    }
    __syncthreads();

    // L3 (256 threads: 2 rows x 128 p)
    if (t < 256) {
        const int row = t >> 7, p = t & 127;
        float h2 = fmaxf(psum[(row * 2) * 128 + p] + psum[(row * 2 + 1) * 128 + p]
                         + __ldg(&b2[p]), 0.0f) * __ldg(&W3[p]);
        #pragma unroll
        for (int o = 16; o > 0; o >>= 1) h2 += __shfl_down_sync(0xffffffff, h2, o);
        if ((t & 31) == 0) red[t >> 5] = h2;
    }
    __syncthreads();
    if (t == 0)
        out[r0] = red[0] + red[1] + red[2] + red[3] + __ldg(&b3[0]);
    if (t == 128 && has2)
        out[r1] = red[4] + red[5] + red[6] + red[7] + __ldg(&b3[0]);
}

// ---------------------------------------------------------------------------
extern "C" void kernel_launch(void* const* d_in, const int* in_sizes, int n_in,
                              void* d_out, int out_size) {
    (void)in_sizes; (void)n_in; (void)out_size;
    const float* audio = (const float*)d_in[0];
    const float* video = (const float*)d_in[1];
    const float* text  = (const float*)d_in[2];
    const float* W1    = (const float*)d_in[3];
    const float* b1    = (const float*)d_in[4];
    const float* W2    = (const float*)d_in[5];
    const float* b2    = (const float*)d_in[6];
    const float* W3    = (const float*)d_in[7];
    const float* b3    = (const float*)d_in[8];
    float* out = (float*)d_out;

    cudaFuncSetAttribute(tfn_gemm, cudaFuncAttributeMaxDynamicSharedMemorySize,
                         SMEM_BYTES);
    cudaFuncSetAttribute(epi, cudaFuncAttributeMaxDynamicSharedMemorySize,
                         EPI_BYTES);

    dim3 grid(2, NG);   // 152 CTAs = one wave
    tfn_gemm<<<grid, 512, SMEM_BYTES>>>(audio, video, text, W1);
    epi<<<152, 512, EPI_BYTES>>>(b1, W2, b2, W3, b3, out);
}